// round 1
// baseline (speedup 1.0000x reference)
#include <cuda_runtime.h>
#include <math.h>

#define BB 4
#define SS 4096
#define DD 1024
#define HH 64
#define NROW (BB*SS)

// Scratch for Q,K,V projections (allocation-free rule: __device__ globals).
__device__ float g_Q[NROW*HH];
__device__ float g_K[NROW*HH];
__device__ float g_V[NROW*HH];

// ---------------------------------------------------------------------------
// Kernel 1: QKV projection.  X:[NROW,1024] @ W:[1024,64] for q,k,v.
// Block = 64 rows x 64 cols, 256 threads, 4x4 register tiles per thread,
// K chunked by 32 with X staged transposed (d-major) in smem.
// Softmax scale (1/8) folded into Q at write time.
// ---------------------------------------------------------------------------
__global__ __launch_bounds__(256) void qkv_kernel(
    const float* __restrict__ X,
    const float* __restrict__ Wq,
    const float* __restrict__ Wk,
    const float* __restrict__ Wv)
{
    __shared__ float Xt[32*68];              // [dc][row], padded stride 68
    __shared__ float Wqs[32*64];             // [dc][h]
    __shared__ float Wks[32*64];
    __shared__ float Wvs[32*64];

    const int tid  = threadIdx.x;
    const int row0 = blockIdx.x * 64;
    const int tr   = tid >> 4;               // 0..15 -> rows tr*4..tr*4+3
    const int tc   = tid & 15;               // 0..15 -> cols tc*4..tc*4+3

    float aq[16], ak[16], av[16];
    #pragma unroll
    for (int i = 0; i < 16; ++i) { aq[i] = 0.f; ak[i] = 0.f; av[i] = 0.f; }

    for (int d0 = 0; d0 < DD; d0 += 32) {
        // Stage X tile transposed: Xt[dc][r]
        #pragma unroll
        for (int it = 0; it < 8; ++it) {
            int idx = tid + 256*it;          // 2048 elems
            int r   = idx >> 5;
            int dc  = idx & 31;
            Xt[dc*68 + r] = X[(row0 + r)*DD + d0 + dc];
        }
        // Stage W chunks (already d-major in gmem)
        #pragma unroll
        for (int it = 0; it < 8; ++it) {
            int idx = tid + 256*it;          // idx = dc*64 + h
            int dc  = idx >> 6;
            int h   = idx & 63;
            int g   = (d0 + dc)*HH + h;
            Wqs[idx] = Wq[g];
            Wks[idx] = Wk[g];
            Wvs[idx] = Wv[g];
        }
        __syncthreads();

        #pragma unroll
        for (int dc = 0; dc < 32; ++dc) {
            float4 x = *(const float4*)(Xt  + dc*68 + tr*4);
            float4 q = *(const float4*)(Wqs + dc*64 + tc*4);
            float4 k = *(const float4*)(Wks + dc*64 + tc*4);
            float4 v = *(const float4*)(Wvs + dc*64 + tc*4);
            float xs[4] = {x.x, x.y, x.z, x.w};
            float qs[4] = {q.x, q.y, q.z, q.w};
            float ks[4] = {k.x, k.y, k.z, k.w};
            float vs[4] = {v.x, v.y, v.z, v.w};
            #pragma unroll
            for (int i = 0; i < 4; ++i)
                #pragma unroll
                for (int j = 0; j < 4; ++j) {
                    aq[i*4+j] += xs[i]*qs[j];
                    ak[i*4+j] += xs[i]*ks[j];
                    av[i*4+j] += xs[i]*vs[j];
                }
        }
        __syncthreads();
    }

    #pragma unroll
    for (int i = 0; i < 4; ++i) {
        int row = row0 + tr*4 + i;
        float* qp = g_Q + row*HH + tc*4;
        float* kp = g_K + row*HH + tc*4;
        float* vp = g_V + row*HH + tc*4;
        float4 wq = make_float4(aq[i*4+0]*0.125f, aq[i*4+1]*0.125f,
                                aq[i*4+2]*0.125f, aq[i*4+3]*0.125f);
        float4 wk = make_float4(ak[i*4+0], ak[i*4+1], ak[i*4+2], ak[i*4+3]);
        float4 wv = make_float4(av[i*4+0], av[i*4+1], av[i*4+2], av[i*4+3]);
        *(float4*)qp = wq;
        *(float4*)kp = wk;
        *(float4*)vp = wv;
    }
}

// ---------------------------------------------------------------------------
// Kernel 2: causal flash attention, fp32.
// One CTA per (batch, 64-query tile).  256 threads.
// Qt/Kt stored d-major (transposed), P stored k-major -> both matmul phases
// are 2x LDS.128 + 16 FFMA per reduction step per thread.
// ---------------------------------------------------------------------------
struct AttnSmem {
    float Qt[64*68];   // [d][q], padded
    float Kt[64*68];   // [d][k], padded
    float Vs[64*64];   // [k][h]
    float Pt[64*68];   // [k][q], padded
    float m_s[64];
    float l_s[64];
    float a_s[64];
};

extern __shared__ char smem_raw[];

__global__ __launch_bounds__(256) void attn_kernel(float* __restrict__ out)
{
    AttnSmem& sm = *reinterpret_cast<AttnSmem*>(smem_raw);
    const int tid = threadIdx.x;
    const int qi  = 63 - (int)blockIdx.x;    // longest blocks first
    const int b   = blockIdx.y;
    const int q0  = qi * 64;
    const int tg  = tid >> 4;                // 0..15 : query group (rows tg*4..+3)
    const int tl  = tid & 15;                // 0..15 : key/head group (cols tl*4..+3)

    // Load Q tile transposed
    const float* Qg = g_Q + (size_t)(b*SS + q0)*HH;
    #pragma unroll
    for (int it = 0; it < 16; ++it) {
        int idx = tid + 256*it;              // idx = q*64 + d
        int q   = idx >> 6;
        int d   = idx & 63;
        sm.Qt[d*68 + q] = Qg[idx];
    }
    if (tid < 64) { sm.m_s[tid] = -INFINITY; sm.l_s[tid] = 0.f; }

    float o[16];
    #pragma unroll
    for (int i = 0; i < 16; ++i) o[i] = 0.f;
    __syncthreads();

    for (int kt = 0; kt <= qi; ++kt) {
        const float* Kg = g_K + (size_t)(b*SS + kt*64)*HH;
        const float* Vg = g_V + (size_t)(b*SS + kt*64)*HH;
        #pragma unroll
        for (int it = 0; it < 16; ++it) {
            int idx = tid + 256*it;          // idx = k*64 + d
            int k   = idx >> 6;
            int d   = idx & 63;
            sm.Kt[d*68 + k] = Kg[idx];
            sm.Vs[idx]      = Vg[idx];
        }
        __syncthreads();

        // --- scores: S[q][k] = Q . K  (scale already folded into Q) ---
        float s[16];
        #pragma unroll
        for (int i = 0; i < 16; ++i) s[i] = 0.f;
        #pragma unroll 8
        for (int d = 0; d < 64; ++d) {
            float4 qv = *(const float4*)(sm.Qt + d*68 + tg*4);
            float4 kv = *(const float4*)(sm.Kt + d*68 + tl*4);
            s[ 0] += qv.x*kv.x; s[ 1] += qv.x*kv.y; s[ 2] += qv.x*kv.z; s[ 3] += qv.x*kv.w;
            s[ 4] += qv.y*kv.x; s[ 5] += qv.y*kv.y; s[ 6] += qv.y*kv.z; s[ 7] += qv.y*kv.w;
            s[ 8] += qv.z*kv.x; s[ 9] += qv.z*kv.y; s[10] += qv.z*kv.z; s[11] += qv.z*kv.w;
            s[12] += qv.w*kv.x; s[13] += qv.w*kv.y; s[14] += qv.w*kv.z; s[15] += qv.w*kv.w;
        }
        if (kt == qi) {
            // diagonal tile: key_local > query_local -> mask
            #pragma unroll
            for (int i = 0; i < 4; ++i)
                #pragma unroll
                for (int j = 0; j < 4; ++j)
                    if (tl*4 + j > tg*4 + i) s[i*4+j] = -INFINITY;
        }

        // --- online softmax per row (16-lane groups share a row group) ---
        #pragma unroll
        for (int i = 0; i < 4; ++i) {
            float rmax = fmaxf(fmaxf(s[i*4+0], s[i*4+1]), fmaxf(s[i*4+2], s[i*4+3]));
            #pragma unroll
            for (int x = 1; x < 16; x <<= 1)
                rmax = fmaxf(rmax, __shfl_xor_sync(0xffffffffu, rmax, x));
            const int q = tg*4 + i;
            float m_old = sm.m_s[q];
            float m_new = fmaxf(m_old, rmax);
            float alpha = __expf(m_old - m_new);
            float p0 = __expf(s[i*4+0] - m_new);
            float p1 = __expf(s[i*4+1] - m_new);
            float p2 = __expf(s[i*4+2] - m_new);
            float p3 = __expf(s[i*4+3] - m_new);
            float rs = (p0 + p1) + (p2 + p3);
            #pragma unroll
            for (int x = 1; x < 16; x <<= 1)
                rs += __shfl_xor_sync(0xffffffffu, rs, x);
            if (tl == 0) {
                sm.m_s[q] = m_new;
                sm.a_s[q] = alpha;
                sm.l_s[q] = sm.l_s[q]*alpha + rs;
            }
            sm.Pt[(tl*4+0)*68 + q] = p0;
            sm.Pt[(tl*4+1)*68 + q] = p1;
            sm.Pt[(tl*4+2)*68 + q] = p2;
            sm.Pt[(tl*4+3)*68 + q] = p3;
        }
        __syncthreads();

        // --- PV: O[q][h] = O*alpha + P @ V ---
        float al[4];
        #pragma unroll
        for (int i = 0; i < 4; ++i) al[i] = sm.a_s[tg*4 + i];
        #pragma unroll
        for (int i = 0; i < 4; ++i)
            #pragma unroll
            for (int j = 0; j < 4; ++j) o[i*4+j] *= al[i];

        #pragma unroll 8
        for (int k = 0; k < 64; ++k) {
            float4 pv = *(const float4*)(sm.Pt + k*68 + tg*4);
            float4 vv = *(const float4*)(sm.Vs + k*64 + tl*4);
            o[ 0] += pv.x*vv.x; o[ 1] += pv.x*vv.y; o[ 2] += pv.x*vv.z; o[ 3] += pv.x*vv.w;
            o[ 4] += pv.y*vv.x; o[ 5] += pv.y*vv.y; o[ 6] += pv.y*vv.z; o[ 7] += pv.y*vv.w;
            o[ 8] += pv.z*vv.x; o[ 9] += pv.z*vv.y; o[10] += pv.z*vv.z; o[11] += pv.z*vv.w;
            o[12] += pv.w*vv.x; o[13] += pv.w*vv.y; o[14] += pv.w*vv.z; o[15] += pv.w*vv.w;
        }
        __syncthreads();
    }

    // normalize + write
    float* Og = out + (size_t)(b*SS + q0)*HH;
    #pragma unroll
    for (int i = 0; i < 4; ++i) {
        float linv = 1.f / sm.l_s[tg*4 + i];
        float4 r = make_float4(o[i*4+0]*linv, o[i*4+1]*linv,
                               o[i*4+2]*linv, o[i*4+3]*linv);
        *(float4*)(Og + (tg*4 + i)*HH + tl*4) = r;
    }
}

// ---------------------------------------------------------------------------
extern "C" void kernel_launch(void* const* d_in, const int* in_sizes, int n_in,
                              void* d_out, int out_size)
{
    const float* X  = (const float*)d_in[0];
    const float* Wq = (const float*)d_in[1];
    const float* Wk = (const float*)d_in[2];
    const float* Wv = (const float*)d_in[3];
    float* out = (float*)d_out;

    qkv_kernel<<<NROW/64, 256>>>(X, Wq, Wk, Wv);

    const int smem_bytes = (int)sizeof(AttnSmem);   // ~69 KB
    cudaFuncSetAttribute(attn_kernel,
                         cudaFuncAttributeMaxDynamicSharedMemorySize, smem_bytes);
    attn_kernel<<<dim3(SS/64, BB), 256, smem_bytes>>>(out);
}